// round 3
// baseline (speedup 1.0000x reference)
#include <cuda_runtime.h>
#include <cstdint>
#include <math_constants.h>

// Problem constants (fixed by the reference)
constexpr int NB = 16;     // batch
constexpr int LQ = 2048;   // query length
constexpr int SK = 2048;   // key length
constexpr int DD = 128;    // head dim

constexpr int TQ = 16;     // query rows per block (logits tile held in smem)
constexpr int TS = 128;    // s-tile width
constexpr int PAD = TS + 4;
constexpr int THREADS = 256;

// dynamic smem: logits[TQ][SK] | Qs[TQ][DD] | Ks[DD][PAD] (reused as V tile [TS][DD])
constexpr int SMEM_FLOATS = TQ * SK + TQ * DD + DD * PAD;

// Mask dtype: 0 = uint8 bool, 1 = int32, 2 = float32
__device__ int g_mask_kind;

__global__ void detect_mask_kind(const unsigned char* __restrict__ m)
{
    __shared__ int off1, off23;
    if (threadIdx.x == 0) { off1 = 0; off23 = 0; }
    __syncthreads();
    int b1 = 0, b23 = 0;
    for (int i = threadIdx.x; i < 16384; i += blockDim.x) {
        unsigned char v = m[i];
        int off = i & 3;
        if (v) {
            if (off == 1) b1 = 1;
            if (off == 2 || off == 3) b23 = 1;
        }
    }
    if (b1)  atomicOr(&off1, 1);
    if (b23) atomicOr(&off23, 1);
    __syncthreads();
    if (threadIdx.x == 0) {
        int kind;
        if (off1)       kind = 0;  // bytes populated at all offsets -> uint8 bool
        else if (off23) kind = 2;  // 0x3f80_0000 pattern -> float32
        else            kind = 1;  // nonzero only at offset 0 mod 4 -> int32
        g_mask_kind = kind;
    }
}

__device__ __forceinline__ bool mask_at(const void* M, int kind, size_t idx)
{
    if (kind == 0) return ((const unsigned char*)M)[idx] != 0;
    if (kind == 1) return ((const int*)M)[idx] != 0;
    return ((const float*)M)[idx] != 0.0f;
}

__global__ __launch_bounds__(THREADS, 1)
void attn_fused_kernel(const float* __restrict__ Q,
                       const float* __restrict__ K,
                       const float* __restrict__ V,
                       const void* __restrict__ M,
                       float* __restrict__ outX,
                       float* __restrict__ outW)
{
    extern __shared__ float sm[];
    float* Lg = sm;                    // TQ * SK   logits -> weights
    float* Qs = Lg + TQ * SK;          // TQ * DD
    float* Ks = Qs + TQ * DD;          // DD * PAD (transposed K tile) / V tile

    const int n   = blockIdx.y;
    const int q0  = blockIdx.x * TQ;
    const int tid = threadIdx.x;
    const int lane = tid & 31;
    const int wid  = tid >> 5;
    const int mkind = g_mask_kind;

    // ---- load Q tile (coalesced float4) ----
    const float* Qg = Q + ((size_t)n * LQ + q0) * DD;
    for (int i = tid; i < TQ * DD / 4; i += THREADS)
        ((float4*)Qs)[i] = ((const float4*)Qg)[i];

    const int sx = tid & 63;   // s-pair index (covers s = 2*sx, 2*sx+1)
    const int qy = tid >> 6;   // 0..3 -> q group (constant within a warp -> Qs broadcast)
    const float scale = 0.08838834764831845f;  // 1/sqrt(128)

    // ================= Phase 1: logits = mask ? -1e11 : clamp(QK^T * scale) =================
    for (int st = 0; st < SK; st += TS) {
        __syncthreads();  // previous Ks readers done
        const float* Kg = K + ((size_t)n * SK + st) * DD;
        // stage K tile transposed: Ks[k][s]
        for (int i = tid; i < TS * DD / 4; i += THREADS) {
            float4 v = ((const float4*)Kg)[i];
            int s = i >> 5;            // i / (DD/4)
            int k = (i & 31) << 2;
            Ks[(k + 0) * PAD + s] = v.x;
            Ks[(k + 1) * PAD + s] = v.y;
            Ks[(k + 2) * PAD + s] = v.z;
            Ks[(k + 3) * PAD + s] = v.w;
        }
        __syncthreads();

        float acc[4][2] = {};
        #pragma unroll 8
        for (int k = 0; k < DD; k += 2) {
            float2 kv0 = *(const float2*)&Ks[(k + 0) * PAD + 2 * sx];
            float2 kv1 = *(const float2*)&Ks[(k + 1) * PAD + 2 * sx];
            #pragma unroll
            for (int qi = 0; qi < 4; qi++) {
                float2 qv = *(const float2*)&Qs[(qy * 4 + qi) * DD + k];
                acc[qi][0] += qv.x * kv0.x + qv.y * kv1.x;
                acc[qi][1] += qv.x * kv0.y + qv.y * kv1.y;
            }
        }

        #pragma unroll
        for (int qi = 0; qi < 4; qi++) {
            int q = qy * 4 + qi;
            size_t mbase = ((size_t)(n * LQ + q0 + q)) * SK + st + 2 * sx;
            #pragma unroll
            for (int j = 0; j < 2; j++) {
                float l = fminf(fmaxf(acc[qi][j] * scale, -1e11f), 1e11f);
                if (mask_at(M, mkind, mbase + j)) l = -1e11f;  // clamp(-inf) = -1e11 exactly
                Lg[q * SK + st + 2 * sx + j] = l;
            }
        }
    }
    __syncthreads();

    // ================= Phase 2: row softmax in smem =================
    for (int r = wid; r < TQ; r += THREADS / 32) {
        float m = -CUDART_INF_F;
        for (int s = lane; s < SK; s += 32) m = fmaxf(m, Lg[r * SK + s]);
        #pragma unroll
        for (int o = 16; o; o >>= 1) m = fmaxf(m, __shfl_xor_sync(0xffffffffu, m, o));

        float sum = 0.f;
        for (int s = lane; s < SK; s += 32) {
            float e = expf(Lg[r * SK + s] - m);   // expf(-1e11 - m) -> exactly 0
            Lg[r * SK + s] = e;
            sum += e;
        }
        #pragma unroll
        for (int o = 16; o; o >>= 1) sum += __shfl_xor_sync(0xffffffffu, sum, o);

        float inv = 1.f / sum;
        for (int s = lane; s < SK; s += 32) Lg[r * SK + s] *= inv;
    }
    __syncthreads();

    // ---- write attn_weights (coalesced float4; smem layout == gmem layout) ----
    float* outWb = outW + ((size_t)(n * LQ + q0)) * SK;
    for (int i = tid; i < TQ * SK / 4; i += THREADS)
        ((float4*)outWb)[i] = ((const float4*)Lg)[i];

    // ================= Phase 3: x = weights @ V =================
    float xacc[4][2] = {};
    const int dx = tid & 63;  // d-pair index (d = 2*dx, 2*dx+1)
    for (int st = 0; st < SK; st += TS) {
        __syncthreads();  // previous V-tile readers done
        const float* Vg = V + ((size_t)n * SK + st) * DD;
        for (int i = tid; i < TS * DD / 4; i += THREADS)
            ((float4*)Ks)[i] = ((const float4*)Vg)[i];   // Vs[s][d], row stride DD
        __syncthreads();

        #pragma unroll 4
        for (int s = 0; s < TS; s++) {
            float2 vv = *(const float2*)&Ks[s * DD + 2 * dx];
            #pragma unroll
            for (int qi = 0; qi < 4; qi++) {
                float w = Lg[(qy * 4 + qi) * SK + st + s];  // warp-broadcast
                xacc[qi][0] += w * vv.x;
                xacc[qi][1] += w * vv.y;
            }
        }
    }

    #pragma unroll
    for (int qi = 0; qi < 4; qi++) {
        int q = qy * 4 + qi;
        float2 o;
        o.x = xacc[qi][0];
        o.y = xacc[qi][1];
        *(float2*)&outX[((size_t)(n * LQ + q0 + q)) * DD + 2 * dx] = o;
    }
}

extern "C" void kernel_launch(void* const* d_in, const int* in_sizes, int n_in,
                              void* d_out, int out_size)
{
    (void)in_sizes; (void)n_in; (void)out_size;
    const float* Q = (const float*)d_in[0];
    const float* K = (const float*)d_in[1];
    const float* V = (const float*)d_in[2];
    const void*  M = d_in[3];

    float* outX = (float*)d_out;                       // (N, L, D) first
    float* outW = outX + (size_t)NB * LQ * DD;         // (N, L, S) second

    cudaFuncSetAttribute(attn_fused_kernel,
                         cudaFuncAttributeMaxDynamicSharedMemorySize,
                         SMEM_FLOATS * (int)sizeof(float));

    detect_mask_kind<<<1, 256>>>((const unsigned char*)M);

    dim3 grid(LQ / TQ, NB);
    attn_fused_kernel<<<grid, THREADS, SMEM_FLOATS * sizeof(float)>>>(
        Q, K, V, M, outX, outW);
}

// round 5
// speedup vs baseline: 1.8005x; 1.8005x over previous
#include <cuda_runtime.h>
#include <cuda_bf16.h>
#include <cstdint>

constexpr int NB = 16, LQ = 2048, SK = 2048, DD = 128;
constexpr int TS = 128, NT = SK / TS, THREADS = 256;
constexpr float SCALE = 0.08838834764831845f;  // 1/sqrt(128)
constexpr int ROWB = 272;                      // 136 bf16 per padded row

// smem byte offsets: 6 bf16 tiles [128][136] + mask bits
constexpr int SM_QH = 0;
constexpr int SM_QL = 34816;
constexpr int SM_KH = 69632;
constexpr int SM_KL = 104448;
constexpr int SM_VH = 139264;   // V transposed: VT[d][s]
constexpr int SM_VL = 174080;
constexpr int SM_MB = 208896;   // uint32[128][4] mask bits
constexpr int SMEM_TOTAL = SM_MB + 2048;

__device__ int   g_mask_kind;
__device__ float g_invZ[NB * LQ];

// ---------------- mask dtype detection (0=u8, 1=i32, 2=f32) ----------------
__global__ void detect_mask_kind(const unsigned char* __restrict__ m)
{
    __shared__ int off1, off23;
    if (threadIdx.x == 0) { off1 = 0; off23 = 0; }
    __syncthreads();
    int b1 = 0, b23 = 0;
    for (int i = threadIdx.x; i < 16384; i += blockDim.x) {
        unsigned char v = m[i];
        int off = i & 3;
        if (v) { if (off == 1) b1 = 1; if (off >= 2) b23 = 1; }
    }
    if (b1)  atomicOr(&off1, 1);
    if (b23) atomicOr(&off23, 1);
    __syncthreads();
    if (threadIdx.x == 0) g_mask_kind = off1 ? 0 : (off23 ? 2 : 1);
}

__device__ __forceinline__ bool mask_at(const void* M, int kind, size_t idx)
{
    if (kind == 1) return ((const int*)M)[idx] != 0;
    if (kind == 0) return ((const unsigned char*)M)[idx] != 0;
    return ((const float*)M)[idx] != 0.0f;
}

// ---------------- bf16 helpers ----------------
__device__ __forceinline__ uint32_t pack_bf16(float a, float b) {
    __nv_bfloat16 ah = __float2bfloat16(a), bh = __float2bfloat16(b);
    return (uint32_t)*(uint16_t*)&ah | ((uint32_t)*(uint16_t*)&bh << 16);
}
// split pair (a,b) into hi/lo packed regs
__device__ __forceinline__ void split2(float a, float b, uint32_t& h, uint32_t& l) {
    __nv_bfloat16 ah = __float2bfloat16(a), bh = __float2bfloat16(b);
    float ahf = __bfloat162float(ah), bhf = __bfloat162float(bh);
    h = (uint32_t)*(uint16_t*)&ah | ((uint32_t)*(uint16_t*)&bh << 16);
    l = pack_bf16(a - ahf, b - bhf);
}

// mma.sync m16n8k16 row.col f32.bf16.bf16.f32 (baseline PTX, sm_80+)
__device__ __forceinline__ void mma_bf16(float* c, const uint32_t* a, uint32_t b0, uint32_t b1) {
    asm volatile(
        "mma.sync.aligned.m16n8k16.row.col.f32.bf16.bf16.f32 "
        "{%0,%1,%2,%3}, {%4,%5,%6,%7}, {%8,%9}, {%0,%1,%2,%3};"
        : "+f"(c[0]), "+f"(c[1]), "+f"(c[2]), "+f"(c[3])
        : "r"(a[0]), "r"(a[1]), "r"(a[2]), "r"(a[3]), "r"(b0), "r"(b1));
}

// stage a 128x128 f32 gmem tile (row stride DD) -> hi/lo bf16 smem [128][136]
__device__ __forceinline__ void stage_hl(const float* g, char* sh, char* sl, int tid)
{
    for (int i = tid; i < 4096; i += THREADS) {   // float4 items
        int r = i >> 5, c4 = (i & 31) << 2;
        float4 v = *(const float4*)(g + (size_t)r * DD + c4);
        uint2 H, L;
        split2(v.x, v.y, H.x, L.x);
        split2(v.z, v.w, H.y, L.y);
        int off = r * ROWB + c4 * 2;
        *(uint2*)(sh + off) = H;
        *(uint2*)(sl + off) = L;
    }
}

__global__ __launch_bounds__(THREADS, 1)
void attn_mma_kernel(const float* __restrict__ Q, const float* __restrict__ K,
                     const float* __restrict__ V, const void* __restrict__ M,
                     float* __restrict__ outX, float* __restrict__ outW)
{
    extern __shared__ char sm[];
    const int n = blockIdx.y, q0 = blockIdx.x * 128;
    const int tid = threadIdx.x, lane = tid & 31, w = tid >> 5;
    const int g = lane >> 2, t = lane & 3;
    const int mkind = g_mask_kind;
    const size_t mrow0 = (size_t)n * LQ + q0;

    // persistent Q tile (hi/lo)
    stage_hl(Q + mrow0 * DD, sm + SM_QH, sm + SM_QL, tid);

    const int rowA = 16 * w + g;     // this lane's A-fragment base row
    float X[16][4];
    #pragma unroll
    for (int i = 0; i < 16; i++)
        #pragma unroll
        for (int j = 0; j < 4; j++) X[i][j] = 0.f;
    float zlo = 0.f, zhi = 0.f;

    for (int tt = 0; tt < NT; tt++) {
        const int st = tt * TS;
        __syncthreads();   // previous tile's readers done with K/VT/MB

        // ---- stage K tile hi/lo ----
        stage_hl(K + ((size_t)n * SK + st) * DD, sm + SM_KH, sm + SM_KL, tid);

        // ---- stage V tile transposed: VT[d][s], hi/lo ----
        {
            const float* Vg = V + ((size_t)n * SK + st) * DD;
            for (int i = tid; i < 2048; i += THREADS) {
                int dg = i >> 6, sp = i & 63;           // d-group (4 dims), s-pair
                const float* vp = Vg + (size_t)(2 * sp) * DD + 4 * dg;
                float4 v0 = *(const float4*)vp;
                float4 v1 = *(const float4*)(vp + DD);
                const float* a0 = &v0.x;
                const float* a1 = &v1.x;
                #pragma unroll
                for (int j = 0; j < 4; j++) {
                    uint32_t h, l;
                    split2(a0[j], a1[j], h, l);          // low half = even s
                    int off = (4 * dg + j) * ROWB + sp * 4;
                    *(uint32_t*)(sm + SM_VH + off) = h;
                    *(uint32_t*)(sm + SM_VL + off) = l;
                }
            }
        }

        // ---- stage mask bits: MB[row][4] ----
        {
            uint32_t* MB = (uint32_t*)(sm + SM_MB);
            for (int it = w; it < 512 / 32 * 32; it += 8) {   // 512 words, 64 per warp
                int r = it >> 2, c = it & 3;
                bool mk = mask_at(M, mkind, (mrow0 + r) * SK + st + c * 32 + lane);
                uint32_t bits = __ballot_sync(0xffffffffu, mk);
                if (lane == 0) MB[r * 4 + c] = bits;
            }
        }
        __syncthreads();

        uint32_t pah[8][4], pal[8][4];   // P fragments (hi/lo) for this tile

        #pragma unroll
        for (int half = 0; half < 2; half++) {
            float sacc[8][4];
            #pragma unroll
            for (int i = 0; i < 8; i++)
                #pragma unroll
                for (int j = 0; j < 4; j++) sacc[i][j] = 0.f;

            uint32_t qa[8][4];
            // load Q-hi fragments (reused for passes hh and h*loB)
            #pragma unroll
            for (int kc = 0; kc < 8; kc++) {
                int base = SM_QH + rowA * ROWB + kc * 32 + t * 4;
                qa[kc][0] = *(const uint32_t*)(sm + base);
                qa[kc][1] = *(const uint32_t*)(sm + base + 8 * ROWB);
                qa[kc][2] = *(const uint32_t*)(sm + base + 16);
                qa[kc][3] = *(const uint32_t*)(sm + base + 8 * ROWB + 16);
            }
            // pass 1: Qh * Kh
            #pragma unroll
            for (int nn = 0; nn < 8; nn++) {
                int bro = SM_KH + (half * 64 + nn * 8 + g) * ROWB + t * 4;
                #pragma unroll
                for (int kc = 0; kc < 8; kc++) {
                    uint32_t b0 = *(const uint32_t*)(sm + bro + kc * 32);
                    uint32_t b1 = *(const uint32_t*)(sm + bro + kc * 32 + 16);
                    mma_bf16(sacc[nn], qa[kc], b0, b1);
                }
            }
            // pass 2: Qh * Kl
            #pragma unroll
            for (int nn = 0; nn < 8; nn++) {
                int bro = SM_KL + (half * 64 + nn * 8 + g) * ROWB + t * 4;
                #pragma unroll
                for (int kc = 0; kc < 8; kc++) {
                    uint32_t b0 = *(const uint32_t*)(sm + bro + kc * 32);
                    uint32_t b1 = *(const uint32_t*)(sm + bro + kc * 32 + 16);
                    mma_bf16(sacc[nn], qa[kc], b0, b1);
                }
            }
            // pass 3: Ql * Kh
            #pragma unroll
            for (int kc = 0; kc < 8; kc++) {
                int base = SM_QL + rowA * ROWB + kc * 32 + t * 4;
                qa[kc][0] = *(const uint32_t*)(sm + base);
                qa[kc][1] = *(const uint32_t*)(sm + base + 8 * ROWB);
                qa[kc][2] = *(const uint32_t*)(sm + base + 16);
                qa[kc][3] = *(const uint32_t*)(sm + base + 8 * ROWB + 16);
            }
            #pragma unroll
            for (int nn = 0; nn < 8; nn++) {
                int bro = SM_KH + (half * 64 + nn * 8 + g) * ROWB + t * 4;
                #pragma unroll
                for (int kc = 0; kc < 8; kc++) {
                    uint32_t b0 = *(const uint32_t*)(sm + bro + kc * 32);
                    uint32_t b1 = *(const uint32_t*)(sm + bro + kc * 32 + 16);
                    mma_bf16(sacc[nn], qa[kc], b0, b1);
                }
            }

            // ---- epilogue: mask, exp, Z, W write, P fragments (in registers) ----
            const uint32_t* MB = (const uint32_t*)(sm + SM_MB);
            #pragma unroll
            for (int nn = 0; nn < 8; nn++) {
                int sIn = half * 64 + nn * 8 + 2 * t;       // s within tile (c0)
                uint32_t mwl = MB[(16 * w + g) * 4 + (sIn >> 5)];
                uint32_t mwh = MB[(16 * w + g + 8) * 4 + (sIn >> 5)];
                int bit = sIn & 31;
                float e0 = ((mwl >> bit) & 1u)       ? 0.f : __expf(sacc[nn][0] * SCALE);
                float e1 = ((mwl >> (bit + 1)) & 1u) ? 0.f : __expf(sacc[nn][1] * SCALE);
                float e2 = ((mwh >> bit) & 1u)       ? 0.f : __expf(sacc[nn][2] * SCALE);
                float e3 = ((mwh >> (bit + 1)) & 1u) ? 0.f : __expf(sacc[nn][3] * SCALE);
                zlo += e0 + e1;
                zhi += e2 + e3;
                float* wr = outW + (mrow0 + 16 * w + g) * (size_t)SK + st + sIn;
                *(float2*)wr = make_float2(e0, e1);
                *(float2*)(wr + 8 * SK) = make_float2(e2, e3);

                uint32_t h01, l01, h23, l23;
                split2(e0, e1, h01, l01);
                split2(e2, e3, h23, l23);
                int kc = half * 4 + (nn >> 1);
                if ((nn & 1) == 0) {
                    pah[kc][0] = h01; pah[kc][1] = h23;
                    pal[kc][0] = l01; pal[kc][1] = l23;
                } else {
                    pah[kc][2] = h01; pah[kc][3] = h23;
                    pal[kc][2] = l01; pal[kc][3] = l23;
                }
            }
        }

        // ---- PV: X += P * V  (A=P frags in regs, B=VT) ----
        #pragma unroll
        for (int nn = 0; nn < 16; nn++) {
            int bh = SM_VH + (nn * 8 + g) * ROWB + t * 4;
            int bl = SM_VL + (nn * 8 + g) * ROWB + t * 4;
            #pragma unroll
            for (int kc = 0; kc < 8; kc++) {
                uint32_t vh0 = *(const uint32_t*)(sm + bh + kc * 32);
                uint32_t vh1 = *(const uint32_t*)(sm + bh + kc * 32 + 16);
                uint32_t vl0 = *(const uint32_t*)(sm + bl + kc * 32);
                uint32_t vl1 = *(const uint32_t*)(sm + bl + kc * 32 + 16);
                mma_bf16(X[nn], pah[kc], vh0, vh1);
                mma_bf16(X[nn], pal[kc], vh0, vh1);
                mma_bf16(X[nn], pah[kc], vl0, vl1);
            }
        }
    }

    // ---- Z reduce within 4-lane group, write invZ + normalized X ----
    zlo += __shfl_xor_sync(0xffffffffu, zlo, 1);
    zlo += __shfl_xor_sync(0xffffffffu, zlo, 2);
    zhi += __shfl_xor_sync(0xffffffffu, zhi, 1);
    zhi += __shfl_xor_sync(0xffffffffu, zhi, 2);
    float invl = 1.f / zlo, invh = 1.f / zhi;
    if (t == 0) {
        g_invZ[mrow0 + 16 * w + g]     = invl;
        g_invZ[mrow0 + 16 * w + g + 8] = invh;
    }
    #pragma unroll
    for (int nn = 0; nn < 16; nn++) {
        float* xr = outX + (mrow0 + 16 * w + g) * (size_t)DD + nn * 8 + 2 * t;
        *(float2*)xr = make_float2(X[nn][0] * invl, X[nn][1] * invl);
        *(float2*)(xr + 8 * DD) = make_float2(X[nn][2] * invh, X[nn][3] * invh);
    }
}

// ---------------- kernel 2: W *= invZ[row] ----------------
__global__ __launch_bounds__(256)
void norm_w_kernel(float4* __restrict__ W)
{
    size_t i = (size_t)blockIdx.x * 256 + threadIdx.x;   // over NB*LQ*SK/4
    float inv = g_invZ[i >> 9];                          // 512 float4 per row
    float4 v = W[i];
    v.x *= inv; v.y *= inv; v.z *= inv; v.w *= inv;
    W[i] = v;
}

extern "C" void kernel_launch(void* const* d_in, const int* in_sizes, int n_in,
                              void* d_out, int out_size)
{
    (void)in_sizes; (void)n_in; (void)out_size;
    const float* Q = (const float*)d_in[0];
    const float* K = (const float*)d_in[1];
    const float* V = (const float*)d_in[2];
    const void*  M = d_in[3];

    float* outX = (float*)d_out;                    // (N, L, D)
    float* outW = outX + (size_t)NB * LQ * DD;      // (N, L, S)

    cudaFuncSetAttribute(attn_mma_kernel, cudaFuncAttributeMaxDynamicSharedMemorySize,
                         SMEM_TOTAL);

    detect_mask_kind<<<1, 256>>>((const unsigned char*)M);
    dim3 grid(LQ / 128, NB);
    attn_mma_kernel<<<grid, THREADS, SMEM_TOTAL>>>(Q, K, V, M, outX, outW);

    size_t nw4 = (size_t)NB * LQ * SK / 4;
    norm_w_kernel<<<(unsigned)(nw4 / 256), 256>>>((float4*)outW);
}

// round 6
// speedup vs baseline: 2.4005x; 1.3333x over previous
#include <cuda_runtime.h>
#include <cuda_bf16.h>
#include <cstdint>

constexpr int NB = 16, LQ = 2048, SK = 2048, DD = 128;
constexpr int TS = 128, NT = SK / TS, THREADS = 256;
constexpr float SCALE = 0.08838834764831845f;  // 1/sqrt(128)
constexpr int ROWB = 272;                      // 136 bf16 per padded row

// smem byte offsets: 6 bf16 tiles [128][136] + mask bits
constexpr int SM_QH = 0;
constexpr int SM_QL = 34816;
constexpr int SM_KH = 69632;
constexpr int SM_KL = 104448;
constexpr int SM_VH = 139264;   // V transposed: VT[d][s]
constexpr int SM_VL = 174080;
constexpr int SM_MB = 208896;   // uint32[128][4] mask bits
constexpr int SMEM_TOTAL = SM_MB + 2048;
constexpr int HL = 34816;       // hi->lo buffer delta

__device__ int   g_mask_kind;
__device__ float g_invZ[NB * LQ];

// ---------------- mask dtype detection (0=u8, 1=i32, 2=f32) ----------------
__global__ void detect_mask_kind(const unsigned char* __restrict__ m)
{
    __shared__ int off1, off23;
    if (threadIdx.x == 0) { off1 = 0; off23 = 0; }
    __syncthreads();
    int b1 = 0, b23 = 0;
    for (int i = threadIdx.x; i < 16384; i += blockDim.x) {
        unsigned char v = m[i];
        int off = i & 3;
        if (v) { if (off == 1) b1 = 1; if (off >= 2) b23 = 1; }
    }
    if (b1)  atomicOr(&off1, 1);
    if (b23) atomicOr(&off23, 1);
    __syncthreads();
    if (threadIdx.x == 0) g_mask_kind = off1 ? 0 : (off23 ? 2 : 1);
}

__device__ __forceinline__ bool mask_at(const void* M, int kind, size_t idx)
{
    if (kind == 1) return ((const int*)M)[idx] != 0;
    if (kind == 0) return ((const unsigned char*)M)[idx] != 0;
    return ((const float*)M)[idx] != 0.0f;
}

// ---------------- helpers ----------------
__device__ __forceinline__ uint32_t smem_u32(const void* p) {
    uint32_t a;
    asm("{ .reg .u64 t; cvta.to.shared.u64 t, %1; cvt.u32.u64 %0, t; }" : "=r"(a) : "l"(p));
    return a;
}
__device__ __forceinline__ uint32_t pack_bf16(float a, float b) {
    __nv_bfloat16 ah = __float2bfloat16(a), bh = __float2bfloat16(b);
    return (uint32_t)*(uint16_t*)&ah | ((uint32_t)*(uint16_t*)&bh << 16);
}
__device__ __forceinline__ void split2(float a, float b, uint32_t& h, uint32_t& l) {
    __nv_bfloat16 ah = __float2bfloat16(a), bh = __float2bfloat16(b);
    float ahf = __bfloat162float(ah), bhf = __bfloat162float(bh);
    h = (uint32_t)*(uint16_t*)&ah | ((uint32_t)*(uint16_t*)&bh << 16);
    l = pack_bf16(a - ahf, b - bhf);
}
__device__ __forceinline__ void mma_bf16(float* c, const uint32_t* a, uint32_t b0, uint32_t b1) {
    asm volatile(
        "mma.sync.aligned.m16n8k16.row.col.f32.bf16.bf16.f32 "
        "{%0,%1,%2,%3}, {%4,%5,%6,%7}, {%8,%9}, {%0,%1,%2,%3};"
        : "+f"(c[0]), "+f"(c[1]), "+f"(c[2]), "+f"(c[3])
        : "r"(a[0]), "r"(a[1]), "r"(a[2]), "r"(a[3]), "r"(b0), "r"(b1));
}
__device__ __forceinline__ void ldm_x4(uint32_t* r, uint32_t addr) {
    asm volatile("ldmatrix.sync.aligned.m8n8.x4.shared.b16 {%0,%1,%2,%3}, [%4];"
                 : "=r"(r[0]), "=r"(r[1]), "=r"(r[2]), "=r"(r[3]) : "r"(addr));
}

// stage a 128x128 f32 gmem tile (row stride DD) -> hi/lo bf16 smem [128][136]
__device__ __forceinline__ void stage_hl(const float* g, char* sh, char* sl, int tid)
{
    for (int i = tid; i < 4096; i += THREADS) {   // float4 items
        int r = i >> 5, c4 = (i & 31) << 2;
        float4 v = *(const float4*)(g + (size_t)r * DD + c4);
        uint2 H, L;
        split2(v.x, v.y, H.x, L.x);
        split2(v.z, v.w, H.y, L.y);
        int off = r * ROWB + c4 * 2;
        *(uint2*)(sh + off) = H;
        *(uint2*)(sl + off) = L;
    }
}

__global__ __launch_bounds__(THREADS, 1)
void attn_mma_kernel(const float* __restrict__ Q, const float* __restrict__ K,
                     const float* __restrict__ V, const void* __restrict__ M,
                     float* __restrict__ outX, float* __restrict__ outW)
{
    extern __shared__ char sm[];
    const int n = blockIdx.y, q0 = blockIdx.x * 128;
    const int tid = threadIdx.x, lane = tid & 31, w = tid >> 5;
    const int g = lane >> 2, t = lane & 3;
    const int mkind = g_mask_kind;
    const size_t mrow0 = (size_t)n * LQ + q0;
    const uint32_t sb = smem_u32(sm);

    // ldmatrix per-lane geometry
    const int mat = lane >> 3, mr = lane & 7;
    const int bRow = ((mat >> 1) << 3) + mr;   // B-type: mat pairs select nn
    const int bCol = (mat & 1) << 4;
    const int aRow = ((mat & 1) << 3) + mr;    // A-type: mat&1 selects row-half
    const int aCol = (mat >> 1) << 4;

    // ---- stage persistent Q tile, hoist Q fragments to registers ----
    stage_hl(Q + mrow0 * DD, sm + SM_QH, sm + SM_QL, tid);
    __syncthreads();
    uint32_t qh[8][4], ql[8][4];
    {
        uint32_t abase = sb + SM_QH + (uint32_t)(16 * w + aRow) * ROWB + aCol;
        #pragma unroll
        for (int kc = 0; kc < 8; kc++) {
            ldm_x4(qh[kc], abase + kc * 32);
            ldm_x4(ql[kc], abase + kc * 32 + HL);
        }
    }

    float X[16][4];
    #pragma unroll
    for (int i = 0; i < 16; i++)
        #pragma unroll
        for (int j = 0; j < 4; j++) X[i][j] = 0.f;
    float zlo = 0.f, zhi = 0.f;

    for (int tt = 0; tt < NT; tt++) {
        const int st = tt * TS;
        __syncthreads();   // previous tile's readers done with K/VT/MB

        // ---- stage K tile hi/lo ----
        stage_hl(K + ((size_t)n * SK + st) * DD, sm + SM_KH, sm + SM_KL, tid);

        // ---- stage V tile transposed: VT[d][s], hi/lo ----
        {
            const float* Vg = V + ((size_t)n * SK + st) * DD;
            for (int i = tid; i < 2048; i += THREADS) {
                int dg = i >> 6, sp = i & 63;           // d-group (4 dims), s-pair
                const float* vp = Vg + (size_t)(2 * sp) * DD + 4 * dg;
                float4 v0 = *(const float4*)vp;
                float4 v1 = *(const float4*)(vp + DD);
                const float* a0 = &v0.x;
                const float* a1 = &v1.x;
                #pragma unroll
                for (int j = 0; j < 4; j++) {
                    uint32_t h, l;
                    split2(a0[j], a1[j], h, l);
                    int off = (4 * dg + j) * ROWB + sp * 4;
                    *(uint32_t*)(sm + SM_VH + off) = h;
                    *(uint32_t*)(sm + SM_VL + off) = l;
                }
            }
        }

        // ---- stage mask bits: MB[row][4] ----
        {
            uint32_t* MB = (uint32_t*)(sm + SM_MB);
            for (int it = w; it < 512; it += 8) {
                int r = it >> 2, c = it & 3;
                bool mk = mask_at(M, mkind, (mrow0 + r) * SK + st + c * 32 + lane);
                uint32_t bits = __ballot_sync(0xffffffffu, mk);
                if (lane == 0) MB[r * 4 + c] = bits;
            }
        }
        __syncthreads();

        #pragma unroll
        for (int half = 0; half < 2; half++) {
            // ================= QK for this 64-col half =================
            float sacc[8][4];
            #pragma unroll
            for (int i = 0; i < 8; i++)
                #pragma unroll
                for (int j = 0; j < 4; j++) sacc[i][j] = 0.f;

            #pragma unroll
            for (int nnp = 0; nnp < 4; nnp++) {
                uint32_t kbase = sb + SM_KH
                               + (uint32_t)(half * 64 + nnp * 16 + bRow) * ROWB + bCol;
                #pragma unroll
                for (int kc = 0; kc < 8; kc++) {
                    uint32_t bh[4], bl[4];
                    ldm_x4(bh, kbase + kc * 32);
                    ldm_x4(bl, kbase + kc * 32 + HL);
                    mma_bf16(sacc[2 * nnp],     qh[kc], bh[0], bh[1]);
                    mma_bf16(sacc[2 * nnp + 1], qh[kc], bh[2], bh[3]);
                    mma_bf16(sacc[2 * nnp],     ql[kc], bh[0], bh[1]);
                    mma_bf16(sacc[2 * nnp + 1], ql[kc], bh[2], bh[3]);
                    mma_bf16(sacc[2 * nnp],     qh[kc], bl[0], bl[1]);
                    mma_bf16(sacc[2 * nnp + 1], qh[kc], bl[2], bl[3]);
                }
            }

            // ============ epilogue: mask, exp, Z, W write, P frags ============
            uint32_t pah[4][4], pal[4][4];
            {
                const uint32_t* MB = (const uint32_t*)(sm + SM_MB);
                #pragma unroll
                for (int nn = 0; nn < 8; nn++) {
                    int sIn = half * 64 + nn * 8 + 2 * t;
                    uint32_t mwl = MB[(16 * w + g) * 4 + (sIn >> 5)];
                    uint32_t mwh = MB[(16 * w + g + 8) * 4 + (sIn >> 5)];
                    int bit = sIn & 31;
                    float e0 = ((mwl >> bit) & 1u)       ? 0.f : __expf(sacc[nn][0] * SCALE);
                    float e1 = ((mwl >> (bit + 1)) & 1u) ? 0.f : __expf(sacc[nn][1] * SCALE);
                    float e2 = ((mwh >> bit) & 1u)       ? 0.f : __expf(sacc[nn][2] * SCALE);
                    float e3 = ((mwh >> (bit + 1)) & 1u) ? 0.f : __expf(sacc[nn][3] * SCALE);
                    zlo += e0 + e1;
                    zhi += e2 + e3;
                    float* wr = outW + (mrow0 + 16 * w + g) * (size_t)SK + st + sIn;
                    *(float2*)wr = make_float2(e0, e1);
                    *(float2*)(wr + 8 * SK) = make_float2(e2, e3);

                    uint32_t h01, l01, h23, l23;
                    split2(e0, e1, h01, l01);
                    split2(e2, e3, h23, l23);
                    int kc = nn >> 1;
                    if ((nn & 1) == 0) {
                        pah[kc][0] = h01; pah[kc][1] = h23;
                        pal[kc][0] = l01; pal[kc][1] = l23;
                    } else {
                        pah[kc][2] = h01; pah[kc][3] = h23;
                        pal[kc][2] = l01; pal[kc][3] = l23;
                    }
                }
            }

            // ================= PV for this half's s-chunk =================
            #pragma unroll
            for (int dp = 0; dp < 8; dp++) {
                uint32_t vbase = sb + SM_VH + (uint32_t)(dp * 16 + bRow) * ROWB + bCol
                               + (half * 4) * 32;
                #pragma unroll
                for (int kcH = 0; kcH < 4; kcH++) {
                    uint32_t vh[4], vl[4];
                    ldm_x4(vh, vbase + kcH * 32);
                    ldm_x4(vl, vbase + kcH * 32 + HL);
                    mma_bf16(X[2 * dp],     pah[kcH], vh[0], vh[1]);
                    mma_bf16(X[2 * dp + 1], pah[kcH], vh[2], vh[3]);
                    mma_bf16(X[2 * dp],     pal[kcH], vh[0], vh[1]);
                    mma_bf16(X[2 * dp + 1], pal[kcH], vh[2], vh[3]);
                    mma_bf16(X[2 * dp],     pah[kcH], vl[0], vl[1]);
                    mma_bf16(X[2 * dp + 1], pah[kcH], vl[2], vl[3]);
                }
            }
        }
    }

    // ---- Z reduce within 4-lane group, write invZ + normalized X ----
    zlo += __shfl_xor_sync(0xffffffffu, zlo, 1);
    zlo += __shfl_xor_sync(0xffffffffu, zlo, 2);
    zhi += __shfl_xor_sync(0xffffffffu, zhi, 1);
    zhi += __shfl_xor_sync(0xffffffffu, zhi, 2);
    float invl = 1.f / zlo, invh = 1.f / zhi;
    if (t == 0) {
        g_invZ[mrow0 + 16 * w + g]     = invl;
        g_invZ[mrow0 + 16 * w + g + 8] = invh;
    }
    #pragma unroll
    for (int nn = 0; nn < 16; nn++) {
        float* xr = outX + (mrow0 + 16 * w + g) * (size_t)DD + nn * 8 + 2 * t;
        *(float2*)xr = make_float2(X[nn][0] * invl, X[nn][1] * invl);
        *(float2*)(xr + 8 * DD) = make_float2(X[nn][2] * invh, X[nn][3] * invh);
    }
}

// ---------------- kernel 2: W *= invZ[row] ----------------
__global__ __launch_bounds__(256)
void norm_w_kernel(float4* __restrict__ W)
{
    size_t i = (size_t)blockIdx.x * 256 + threadIdx.x;   // over NB*LQ*SK/4
    float inv = g_invZ[i >> 9];                          // 512 float4 per row
    float4 v = W[i];
    v.x *= inv; v.y *= inv; v.z *= inv; v.w *= inv;
    W[i] = v;
}

extern "C" void kernel_launch(void* const* d_in, const int* in_sizes, int n_in,
                              void* d_out, int out_size)
{
    (void)in_sizes; (void)n_in; (void)out_size;
    const float* Q = (const float*)d_in[0];
    const float* K = (const float*)d_in[1];
    const float* V = (const float*)d_in[2];
    const void*  M = d_in[3];

    float* outX = (float*)d_out;                    // (N, L, D)
    float* outW = outX + (size_t)NB * LQ * DD;      // (N, L, S)

    cudaFuncSetAttribute(attn_mma_kernel, cudaFuncAttributeMaxDynamicSharedMemorySize,
                         SMEM_TOTAL);

    detect_mask_kind<<<1, 256>>>((const unsigned char*)M);
    dim3 grid(LQ / 128, NB);
    attn_mma_kernel<<<grid, THREADS, SMEM_TOTAL>>>(Q, K, V, M, outX, outW);

    size_t nw4 = (size_t)NB * LQ * SK / 4;
    norm_w_kernel<<<(unsigned)(nw4 / 256), 256>>>((float4*)outW);
}

// round 7
// speedup vs baseline: 2.4422x; 1.0174x over previous
#include <cuda_runtime.h>
#include <cuda_bf16.h>
#include <cstdint>

constexpr int NB = 16, LQ = 2048, SK = 2048, DD = 128;
constexpr int TS = 128, NT = SK / TS, THREADS = 256;
constexpr float SCALE = 0.08838834764831845f;  // 1/sqrt(128)
constexpr int ROWB = 272;                      // 136 bf16 per padded row

// smem byte offsets: 6 bf16 tiles [128][136] + mask bits
constexpr int SM_QH = 0;
constexpr int SM_QL = 34816;
constexpr int SM_KH = 69632;
constexpr int SM_KL = 104448;
constexpr int SM_VH = 139264;   // V transposed: VT[d][s]
constexpr int SM_VL = 174080;
constexpr int SM_MB = 208896;   // uint32[128][4] mask bits
constexpr int SMEM_TOTAL = SM_MB + 2048;
constexpr int HL = 34816;       // hi->lo buffer delta

__device__ int   g_mask_kind;
__device__ float g_invZ[NB * LQ];

// ---------------- mask dtype detection (0=u8, 1=i32, 2=f32) ----------------
__global__ void detect_mask_kind(const unsigned char* __restrict__ m)
{
    __shared__ int off1, off23;
    if (threadIdx.x == 0) { off1 = 0; off23 = 0; }
    __syncthreads();
    int b1 = 0, b23 = 0;
    for (int i = threadIdx.x; i < 16384; i += blockDim.x) {
        unsigned char v = m[i];
        int off = i & 3;
        if (v) { if (off == 1) b1 = 1; if (off >= 2) b23 = 1; }
    }
    if (b1)  atomicOr(&off1, 1);
    if (b23) atomicOr(&off23, 1);
    __syncthreads();
    if (threadIdx.x == 0) g_mask_kind = off1 ? 0 : (off23 ? 2 : 1);
}

__device__ __forceinline__ bool mask_at(const void* M, int kind, size_t idx)
{
    if (kind == 1) return ((const int*)M)[idx] != 0;
    if (kind == 0) return ((const unsigned char*)M)[idx] != 0;
    return ((const float*)M)[idx] != 0.0f;
}

// ---------------- helpers ----------------
__device__ __forceinline__ uint32_t smem_u32(const void* p) {
    uint32_t a;
    asm("{ .reg .u64 t; cvta.to.shared.u64 t, %1; cvt.u32.u64 %0, t; }" : "=r"(a) : "l"(p));
    return a;
}
__device__ __forceinline__ uint32_t pack_bf16(float a, float b) {
    __nv_bfloat16 ah = __float2bfloat16(a), bh = __float2bfloat16(b);
    return (uint32_t)*(uint16_t*)&ah | ((uint32_t)*(uint16_t*)&bh << 16);
}
__device__ __forceinline__ void split2(float a, float b, uint32_t& h, uint32_t& l) {
    __nv_bfloat16 ah = __float2bfloat16(a), bh = __float2bfloat16(b);
    float ahf = __bfloat162float(ah), bhf = __bfloat162float(bh);
    h = (uint32_t)*(uint16_t*)&ah | ((uint32_t)*(uint16_t*)&bh << 16);
    l = pack_bf16(a - ahf, b - bhf);
}
__device__ __forceinline__ void mma_bf16(float* c, const uint32_t* a, uint32_t b0, uint32_t b1) {
    asm volatile(
        "mma.sync.aligned.m16n8k16.row.col.f32.bf16.bf16.f32 "
        "{%0,%1,%2,%3}, {%4,%5,%6,%7}, {%8,%9}, {%0,%1,%2,%3};"
        : "+f"(c[0]), "+f"(c[1]), "+f"(c[2]), "+f"(c[3])
        : "r"(a[0]), "r"(a[1]), "r"(a[2]), "r"(a[3]), "r"(b0), "r"(b1));
}
__device__ __forceinline__ void ldm_x4(uint32_t* r, uint32_t addr) {
    asm volatile("ldmatrix.sync.aligned.m8n8.x4.shared.b16 {%0,%1,%2,%3}, [%4];"
                 : "=r"(r[0]), "=r"(r[1]), "=r"(r[2]), "=r"(r[3]) : "r"(addr));
}

// stage a 128x128 f32 gmem tile (row stride DD) -> hi/lo bf16 smem [128][136]
__device__ __forceinline__ void stage_hl(const float* g, char* sh, char* sl, int tid)
{
    for (int i = tid; i < 4096; i += THREADS) {   // float4 items
        int r = i >> 5, c4 = (i & 31) << 2;
        float4 v = *(const float4*)(g + (size_t)r * DD + c4);
        uint2 H, L;
        split2(v.x, v.y, H.x, L.x);
        split2(v.z, v.w, H.y, L.y);
        int off = r * ROWB + c4 * 2;
        *(uint2*)(sh + off) = H;
        *(uint2*)(sl + off) = L;
    }
}

__global__ __launch_bounds__(THREADS, 1)
void attn_mma_kernel(const float* __restrict__ Q, const float* __restrict__ K,
                     const float* __restrict__ V, const void* __restrict__ M,
                     float* __restrict__ outX, float* __restrict__ outW)
{
    extern __shared__ char sm[];
    const int n = blockIdx.y, q0 = blockIdx.x * 128;
    const int tid = threadIdx.x, lane = tid & 31, w = tid >> 5;
    const int g = lane >> 2, t = lane & 3;
    const int mkind = g_mask_kind;
    const size_t mrow0 = (size_t)n * LQ + q0;
    const uint32_t sb = smem_u32(sm);

    // ldmatrix per-lane geometry
    const int mat = lane >> 3, mr = lane & 7;
    const int bRow = ((mat >> 1) << 3) + mr;   // B-type: mat pairs select nn
    const int bCol = (mat & 1) << 4;
    const int aRow = ((mat & 1) << 3) + mr;    // A-type: mat&1 selects row-half
    const int aCol = (mat >> 1) << 4;

    // ---- stage persistent Q tile, hoist Q fragments to registers ----
    stage_hl(Q + mrow0 * DD, sm + SM_QH, sm + SM_QL, tid);
    __syncthreads();
    uint32_t qh[8][4], ql[8][4];
    {
        uint32_t abase = sb + SM_QH + (uint32_t)(16 * w + aRow) * ROWB + aCol;
        #pragma unroll
        for (int kc = 0; kc < 8; kc++) {
            ldm_x4(qh[kc], abase + kc * 32);
            ldm_x4(ql[kc], abase + kc * 32 + HL);
        }
    }

    float X[16][4];
    #pragma unroll
    for (int i = 0; i < 16; i++)
        #pragma unroll
        for (int j = 0; j < 4; j++) X[i][j] = 0.f;
    float zlo = 0.f, zhi = 0.f;

    for (int tt = 0; tt < NT; tt++) {
        const int st = tt * TS;
        __syncthreads();   // previous tile's readers done with K/VT/MB

        // ---- stage K tile hi/lo ----
        stage_hl(K + ((size_t)n * SK + st) * DD, sm + SM_KH, sm + SM_KL, tid);

        // ---- stage V tile transposed: VT[d][s], hi/lo ----
        {
            const float* Vg = V + ((size_t)n * SK + st) * DD;
            for (int i = tid; i < 2048; i += THREADS) {
                int dg = i >> 6, sp = i & 63;           // d-group (4 dims), s-pair
                const float* vp = Vg + (size_t)(2 * sp) * DD + 4 * dg;
                float4 v0 = *(const float4*)vp;
                float4 v1 = *(const float4*)(vp + DD);
                const float* a0 = &v0.x;
                const float* a1 = &v1.x;
                #pragma unroll
                for (int j = 0; j < 4; j++) {
                    uint32_t h, l;
                    split2(a0[j], a1[j], h, l);
                    int off = (4 * dg + j) * ROWB + sp * 4;
                    *(uint32_t*)(sm + SM_VH + off) = h;
                    *(uint32_t*)(sm + SM_VL + off) = l;
                }
            }
        }

        // ---- stage mask bits: MB[row][4] ----
        {
            uint32_t* MB = (uint32_t*)(sm + SM_MB);
            for (int it = w; it < 512; it += 8) {
                int r = it >> 2, c = it & 3;
                bool mk = mask_at(M, mkind, (mrow0 + r) * SK + st + c * 32 + lane);
                uint32_t bits = __ballot_sync(0xffffffffu, mk);
                if (lane == 0) MB[r * 4 + c] = bits;
            }
        }
        __syncthreads();

        #pragma unroll
        for (int half = 0; half < 2; half++) {
            // ================= QK for this 64-col half =================
            // kc outer; per kc load all 4 nnp B-fragments, then issue 48 MMAs
            // round-robin over 8 accumulators (same-acc reuse distance = 8).
            float sacc[8][4];
            #pragma unroll
            for (int i = 0; i < 8; i++)
                #pragma unroll
                for (int j = 0; j < 4; j++) sacc[i][j] = 0.f;

            #pragma unroll
            for (int kc = 0; kc < 8; kc++) {
                uint32_t bh[4][4], bl[4][4];
                #pragma unroll
                for (int nnp = 0; nnp < 4; nnp++) {
                    uint32_t kbase = sb + SM_KH
                        + (uint32_t)(half * 64 + nnp * 16 + bRow) * ROWB + bCol + kc * 32;
                    ldm_x4(bh[nnp], kbase);
                    ldm_x4(bl[nnp], kbase + HL);
                }
                #pragma unroll
                for (int nnp = 0; nnp < 4; nnp++) {
                    mma_bf16(sacc[2 * nnp],     qh[kc], bh[nnp][0], bh[nnp][1]);
                    mma_bf16(sacc[2 * nnp + 1], qh[kc], bh[nnp][2], bh[nnp][3]);
                }
                #pragma unroll
                for (int nnp = 0; nnp < 4; nnp++) {
                    mma_bf16(sacc[2 * nnp],     ql[kc], bh[nnp][0], bh[nnp][1]);
                    mma_bf16(sacc[2 * nnp + 1], ql[kc], bh[nnp][2], bh[nnp][3]);
                }
                #pragma unroll
                for (int nnp = 0; nnp < 4; nnp++) {
                    mma_bf16(sacc[2 * nnp],     qh[kc], bl[nnp][0], bl[nnp][1]);
                    mma_bf16(sacc[2 * nnp + 1], qh[kc], bl[nnp][2], bl[nnp][3]);
                }
            }

            // ============ epilogue: mask, exp, Z, W write, P frags ============
            uint32_t pah[4][4], pal[4][4];
            {
                const uint32_t* MB = (const uint32_t*)(sm + SM_MB);
                #pragma unroll
                for (int nn = 0; nn < 8; nn++) {
                    int sIn = half * 64 + nn * 8 + 2 * t;
                    uint32_t mwl = MB[(16 * w + g) * 4 + (sIn >> 5)];
                    uint32_t mwh = MB[(16 * w + g + 8) * 4 + (sIn >> 5)];
                    int bit = sIn & 31;
                    float e0 = ((mwl >> bit) & 1u)       ? 0.f : __expf(sacc[nn][0] * SCALE);
                    float e1 = ((mwl >> (bit + 1)) & 1u) ? 0.f : __expf(sacc[nn][1] * SCALE);
                    float e2 = ((mwh >> bit) & 1u)       ? 0.f : __expf(sacc[nn][2] * SCALE);
                    float e3 = ((mwh >> (bit + 1)) & 1u) ? 0.f : __expf(sacc[nn][3] * SCALE);
                    zlo += e0 + e1;
                    zhi += e2 + e3;
                    float* wr = outW + (mrow0 + 16 * w + g) * (size_t)SK + st + sIn;
                    *(float2*)wr = make_float2(e0, e1);
                    *(float2*)(wr + 8 * SK) = make_float2(e2, e3);

                    uint32_t h01, l01, h23, l23;
                    split2(e0, e1, h01, l01);
                    split2(e2, e3, h23, l23);
                    int kc = nn >> 1;
                    if ((nn & 1) == 0) {
                        pah[kc][0] = h01; pah[kc][1] = h23;
                        pal[kc][0] = l01; pal[kc][1] = l23;
                    } else {
                        pah[kc][2] = h01; pah[kc][3] = h23;
                        pal[kc][2] = l01; pal[kc][3] = l23;
                    }
                }
            }

            // ================= PV for this half's s-chunk =================
            // kcH outer; dp processed in pairs -> 12 MMAs round-robin over 4 accs.
            #pragma unroll
            for (int kcH = 0; kcH < 4; kcH++) {
                #pragma unroll
                for (int dpp = 0; dpp < 4; dpp++) {
                    const int dp0 = 2 * dpp, dp1 = 2 * dpp + 1;
                    uint32_t v0h[4], v0l[4], v1h[4], v1l[4];
                    uint32_t vb0 = sb + SM_VH + (uint32_t)(dp0 * 16 + bRow) * ROWB + bCol
                                 + (half * 4 + kcH) * 32;
                    uint32_t vb1 = sb + SM_VH + (uint32_t)(dp1 * 16 + bRow) * ROWB + bCol
                                 + (half * 4 + kcH) * 32;
                    ldm_x4(v0h, vb0);
                    ldm_x4(v0l, vb0 + HL);
                    ldm_x4(v1h, vb1);
                    ldm_x4(v1l, vb1 + HL);

                    mma_bf16(X[2 * dp0],     pah[kcH], v0h[0], v0h[1]);
                    mma_bf16(X[2 * dp0 + 1], pah[kcH], v0h[2], v0h[3]);
                    mma_bf16(X[2 * dp1],     pah[kcH], v1h[0], v1h[1]);
                    mma_bf16(X[2 * dp1 + 1], pah[kcH], v1h[2], v1h[3]);

                    mma_bf16(X[2 * dp0],     pal[kcH], v0h[0], v0h[1]);
                    mma_bf16(X[2 * dp0 + 1], pal[kcH], v0h[2], v0h[3]);
                    mma_bf16(X[2 * dp1],     pal[kcH], v1h[0], v1h[1]);
                    mma_bf16(X[2 * dp1 + 1], pal[kcH], v1h[2], v1h[3]);

                    mma_bf16(X[2 * dp0],     pah[kcH], v0l[0], v0l[1]);
                    mma_bf16(X[2 * dp0 + 1], pah[kcH], v0l[2], v0l[3]);
                    mma_bf16(X[2 * dp1],     pah[kcH], v1l[0], v1l[1]);
                    mma_bf16(X[2 * dp1 + 1], pah[kcH], v1l[2], v1l[3]);
                }
            }
        }
    }

    // ---- Z reduce within 4-lane group, write invZ + normalized X ----
    zlo += __shfl_xor_sync(0xffffffffu, zlo, 1);
    zlo += __shfl_xor_sync(0xffffffffu, zlo, 2);
    zhi += __shfl_xor_sync(0xffffffffu, zhi, 1);
    zhi += __shfl_xor_sync(0xffffffffu, zhi, 2);
    float invl = 1.f / zlo, invh = 1.f / zhi;
    if (t == 0) {
        g_invZ[mrow0 + 16 * w + g]     = invl;
        g_invZ[mrow0 + 16 * w + g + 8] = invh;
    }
    #pragma unroll
    for (int nn = 0; nn < 16; nn++) {
        float* xr = outX + (mrow0 + 16 * w + g) * (size_t)DD + nn * 8 + 2 * t;
        *(float2*)xr = make_float2(X[nn][0] * invl, X[nn][1] * invl);
        *(float2*)(xr + 8 * DD) = make_float2(X[nn][2] * invh, X[nn][3] * invh);
    }
}

// ---------------- kernel 2: W *= invZ[row] ----------------
__global__ __launch_bounds__(256)
void norm_w_kernel(float4* __restrict__ W)
{
    size_t i = (size_t)blockIdx.x * 256 + threadIdx.x;   // over NB*LQ*SK/4
    float inv = g_invZ[i >> 9];                          // 512 float4 per row
    float4 v = W[i];
    v.x *= inv; v.y *= inv; v.z *= inv; v.w *= inv;
    W[i] = v;
}

extern "C" void kernel_launch(void* const* d_in, const int* in_sizes, int n_in,
                              void* d_out, int out_size)
{
    (void)in_sizes; (void)n_in; (void)out_size;
    const float* Q = (const float*)d_in[0];
    const float* K = (const float*)d_in[1];
    const float* V = (const float*)d_in[2];
    const void*  M = d_in[3];

    float* outX = (float*)d_out;                    // (N, L, D)
    float* outW = outX + (size_t)NB * LQ * DD;      // (N, L, S)

    cudaFuncSetAttribute(attn_mma_kernel, cudaFuncAttributeMaxDynamicSharedMemorySize,
                         SMEM_TOTAL);

    detect_mask_kind<<<1, 256>>>((const unsigned char*)M);
    dim3 grid(LQ / 128, NB);
    attn_mma_kernel<<<grid, THREADS, SMEM_TOTAL>>>(Q, K, V, M, outX, outW);

    size_t nw4 = (size_t)NB * LQ * SK / 4;
    norm_w_kernel<<<(unsigned)(nw4 / 256), 256>>>((float4*)outW);
}

// round 8
// speedup vs baseline: 4.7096x; 1.9284x over previous
#include <cuda_runtime.h>
#include <cuda_bf16.h>
#include <cstdint>

constexpr int NB = 16, LQ = 2048, SK = 2048, DD = 128;
constexpr int TS = 32, NT = SK / TS;      // 64 key tiles
constexpr int THREADS = 256;
constexpr float SCALE = 0.08838834764831845f;  // 1/sqrt(128)

// ---- smem layout (bytes) ----
constexpr int SQH = 0;         // Q hi: 64 rows x 272B
constexpr int SQL = 17408;     // Q lo
constexpr int SKH = 34816;     // K hi: 32 rows x 272B
constexpr int SKL = 43520;     // K lo
constexpr int SVH = 52224;     // VT hi: 128 rows x 80B
constexpr int SVL = 62464;     // VT lo
constexpr int SPH = 72704;     // P hi: 64 rows x 80B
constexpr int SPL = 77824;     // P lo
constexpr int SMB = 82944;     // mask bits: 64 words
constexpr int SZ  = 83200;     // Z: 2 x 64 floats
constexpr int SMEM_TOTAL = 83712;

// ---- pre-split operands in device globals ----
__device__ __align__(16) __nv_bfloat16 gQh[NB * LQ * DD], gQl[NB * LQ * DD];
__device__ __align__(16) __nv_bfloat16 gKh[NB * SK * DD], gKl[NB * SK * DD];
__device__ __align__(16) __nv_bfloat16 gVh[NB * DD * SK], gVl[NB * DD * SK]; // [n][d][s]
__device__ uint32_t gMB[NB * LQ * (SK / 32)];
__device__ int   g_mask_kind;
__device__ float g_invZ[NB * LQ];

// ---------------- mask dtype detection (0=u8, 1=i32, 2=f32) ----------------
__global__ void detect_mask_kind(const unsigned char* __restrict__ m)
{
    __shared__ int off1, off23;
    if (threadIdx.x == 0) { off1 = 0; off23 = 0; }
    __syncthreads();
    int b1 = 0, b23 = 0;
    for (int i = threadIdx.x; i < 16384; i += blockDim.x) {
        unsigned char v = m[i];
        int off = i & 3;
        if (v) { if (off == 1) b1 = 1; if (off >= 2) b23 = 1; }
    }
    if (b1)  atomicOr(&off1, 1);
    if (b23) atomicOr(&off23, 1);
    __syncthreads();
    if (threadIdx.x == 0) g_mask_kind = off1 ? 0 : (off23 ? 2 : 1);
}

__device__ __forceinline__ bool mask_at(const void* M, int kind, size_t idx)
{
    if (kind == 1) return ((const int*)M)[idx] != 0;
    if (kind == 0) return ((const unsigned char*)M)[idx] != 0;
    return ((const float*)M)[idx] != 0.0f;
}

// ---------------- small helpers ----------------
__device__ __forceinline__ uint32_t smem_u32(const void* p) {
    uint32_t a;
    asm("{ .reg .u64 t; cvta.to.shared.u64 t, %1; cvt.u32.u64 %0, t; }" : "=r"(a) : "l"(p));
    return a;
}
__device__ __forceinline__ uint32_t pack_bf16(float a, float b) {
    __nv_bfloat16 ah = __float2bfloat16(a), bh = __float2bfloat16(b);
    return (uint32_t)*(uint16_t*)&ah | ((uint32_t)*(uint16_t*)&bh << 16);
}
__device__ __forceinline__ void split2(float a, float b, uint32_t& h, uint32_t& l) {
    __nv_bfloat16 ah = __float2bfloat16(a), bh = __float2bfloat16(b);
    float ahf = __bfloat162float(ah), bhf = __bfloat162float(bh);
    h = (uint32_t)*(uint16_t*)&ah | ((uint32_t)*(uint16_t*)&bh << 16);
    l = pack_bf16(a - ahf, b - bhf);
}
__device__ __forceinline__ void mma_bf16(float* c, const uint32_t* a, uint32_t b0, uint32_t b1) {
    asm volatile(
        "mma.sync.aligned.m16n8k16.row.col.f32.bf16.bf16.f32 "
        "{%0,%1,%2,%3}, {%4,%5,%6,%7}, {%8,%9}, {%0,%1,%2,%3};"
        : "+f"(c[0]), "+f"(c[1]), "+f"(c[2]), "+f"(c[3])
        : "r"(a[0]), "r"(a[1]), "r"(a[2]), "r"(a[3]), "r"(b0), "r"(b1));
}
__device__ __forceinline__ void ldm_x4(uint32_t* r, uint32_t addr) {
    asm volatile("ldmatrix.sync.aligned.m8n8.x4.shared.b16 {%0,%1,%2,%3}, [%4];"
                 : "=r"(r[0]), "=r"(r[1]), "=r"(r[2]), "=r"(r[3]) : "r"(addr));
}
__device__ __forceinline__ void cp16(uint32_t dst, const void* src) {
    asm volatile("cp.async.ca.shared.global [%0], [%1], 16;" :: "r"(dst), "l"(src) : "memory");
}
__device__ __forceinline__ void cp4(uint32_t dst, const void* src) {
    asm volatile("cp.async.ca.shared.global [%0], [%1], 4;" :: "r"(dst), "l"(src) : "memory");
}
__device__ __forceinline__ void cp_commit_wait0() {
    asm volatile("cp.async.commit_group;" ::: "memory");
    asm volatile("cp.async.wait_group 0;" ::: "memory");
}

// ---------------- prep kernels ----------------
// A: split Q,K fp32 -> bf16 hi/lo (same layout)
__global__ __launch_bounds__(256)
void prep_splitqk(const float* __restrict__ Q, const float* __restrict__ K)
{
    size_t i = (size_t)blockIdx.x * 256 + threadIdx.x;   // float4 idx, NB*LQ*DD/4 total
    float4 q = ((const float4*)Q)[i];
    float4 k = ((const float4*)K)[i];
    uint2 H, L;
    split2(q.x, q.y, H.x, L.x); split2(q.z, q.w, H.y, L.y);
    ((uint2*)gQh)[i] = H; ((uint2*)gQl)[i] = L;
    split2(k.x, k.y, H.x, L.x); split2(k.z, k.w, H.y, L.y);
    ((uint2*)gKh)[i] = H; ((uint2*)gKl)[i] = L;
}

// B: V fp32 [n][s][d] -> VT bf16 hi/lo [n][d][s]
__global__ __launch_bounds__(256)
void prep_vt(const float* __restrict__ V)
{
    size_t i = (size_t)blockIdx.x * 256 + threadIdx.x;   // (n,d,s8): NB*DD*(SK/8)
    int s8 = (int)(i & 255);
    int d  = (int)((i >> 8) & 127);
    int n  = (int)(i >> 15);
    const float* vp = V + ((size_t)n * SK + s8 * 8) * DD + d;
    float f[8];
    #pragma unroll
    for (int j = 0; j < 8; j++) f[j] = vp[(size_t)j * DD];
    uint4 H, L;
    split2(f[0], f[1], H.x, L.x); split2(f[2], f[3], H.y, L.y);
    split2(f[4], f[5], H.z, L.z); split2(f[6], f[7], H.w, L.w);
    ((uint4*)gVh)[i] = H; ((uint4*)gVl)[i] = L;
}

// C: pack mask into bits [n*LQ][SK/32]
__global__ __launch_bounds__(256)
void prep_mask(const void* __restrict__ M)
{
    int wgid = (int)((blockIdx.x * 256 + threadIdx.x) >> 5);  // q-row index
    int lane = threadIdx.x & 31;
    int kind = g_mask_kind;
    size_t rb = (size_t)wgid * SK;
    for (int c = 0; c < 64; c++) {
        bool mk = mask_at(M, kind, rb + c * 32 + lane);
        uint32_t bits = __ballot_sync(0xffffffffu, mk);
        if (lane == 0) gMB[wgid * 64 + c] = bits;
    }
}

// ---------------- main attention kernel ----------------
__global__ __launch_bounds__(THREADS, 2)
void attn_mma2(float* __restrict__ outX, float* __restrict__ outW)
{
    extern __shared__ char sm[];
    const int n = blockIdx.y, q0 = blockIdx.x * 64;
    const int tid = threadIdx.x, lane = tid & 31, w = tid >> 5;
    const int pid = w >> 1, ps = w & 1;       // pair id 0..3, side 0/1
    const int g = lane >> 2, t = lane & 3;
    const size_t mrow0 = (size_t)n * LQ + q0;
    const uint32_t sb = smem_u32(sm);

    // ldmatrix per-lane geometry (validated)
    const int mat = lane >> 3, mr = lane & 7;
    const int bRow = ((mat >> 1) << 3) + mr;
    const int bCol = (mat & 1) << 4;
    const int aRow = ((mat & 1) << 3) + mr;
    const int aCol = (mat >> 1) << 4;

    // ---- stage Q (persistent) ----
    {
        const char* qh = (const char*)gQh + mrow0 * DD * 2;
        const char* ql = (const char*)gQl + mrow0 * DD * 2;
        for (int c = tid; c < 1024; c += THREADS) {   // 64 rows x 16 chunks
            int r = c >> 4, cx = (c & 15) * 16;
            cp16(sb + SQH + r * 272 + cx, qh + r * 256 + cx);
            cp16(sb + SQL + r * 272 + cx, ql + r * 256 + cx);
        }
        cp_commit_wait0();
        __syncthreads();
    }

    float X[8][4];
    #pragma unroll
    for (int i = 0; i < 8; i++)
        #pragma unroll
        for (int j = 0; j < 4; j++) X[i][j] = 0.f;
    float zl = 0.f, zh = 0.f;

    const uint32_t qbase = sb + SQH + (uint32_t)(pid * 16 + aRow) * 272 + aCol;
    const uint32_t kbase = sb + SKH + (uint32_t)(ps * 16 + bRow) * 272 + bCol;
    const uint32_t pbase = sb + SPH + (uint32_t)(pid * 16 + aRow) * 80 + aCol;

    for (int tt = 0; tt < NT; tt++) {
        const int st = tt * TS;

        // ---- cp.async stage K, VT, mask bits ----
        {
            const char* kh = (const char*)gKh + ((size_t)n * SK + st) * DD * 2;
            const char* kl = (const char*)gKl + ((size_t)n * SK + st) * DD * 2;
            const char* vh = (const char*)gVh + ((size_t)n * DD * SK + st) * 2;
            const char* vl = (const char*)gVl + ((size_t)n * DD * SK + st) * 2;
            for (int c = tid; c < 512; c += THREADS) {
                int r = c >> 4, cx = (c & 15) * 16;        // K: 32 rows x 16
                cp16(sb + SKH + r * 272 + cx, kh + r * 256 + cx);
                cp16(sb + SKL + r * 272 + cx, kl + r * 256 + cx);
                int vr = c >> 2, vx = (c & 3) * 16;        // VT: 128 rows x 4
                cp16(sb + SVH + vr * 80 + vx, vh + (size_t)vr * 4096 + vx);
                cp16(sb + SVL + vr * 80 + vx, vl + (size_t)vr * 4096 + vx);
            }
            if (tid < 64)
                cp4(sb + SMB + tid * 4, (const char*)gMB + ((mrow0 + tid) * 64 + tt) * 4);
            cp_commit_wait0();
        }
        __syncthreads();

        // ---- QK: rows pid*16..+16 x s-sub ps*16..+16, 3-pass hi/lo ----
        float sacc[2][4] = {{0.f,0.f,0.f,0.f},{0.f,0.f,0.f,0.f}};
        #pragma unroll
        for (int kc = 0; kc < 8; kc++) {
            uint32_t qh[4], ql[4], bh[4], bl[4];
            ldm_x4(qh, qbase + kc * 32);
            ldm_x4(ql, qbase + kc * 32 + 17408);
            ldm_x4(bh, kbase + kc * 32);
            ldm_x4(bl, kbase + kc * 32 + 8704);
            mma_bf16(sacc[0], qh, bh[0], bh[1]);
            mma_bf16(sacc[1], qh, bh[2], bh[3]);
            mma_bf16(sacc[0], ql, bh[0], bh[1]);
            mma_bf16(sacc[1], ql, bh[2], bh[3]);
            mma_bf16(sacc[0], qh, bl[0], bl[1]);
            mma_bf16(sacc[1], qh, bl[2], bl[3]);
        }

        // ---- epilogue: mask, exp, Z, W write, P -> smem ----
        {
            const uint32_t* MB = (const uint32_t*)(sm + SMB);
            uint32_t mw0 = MB[pid * 16 + g];
            uint32_t mw1 = MB[pid * 16 + g + 8];
            #pragma unroll
            for (int nn = 0; nn < 2; nn++) {
                int sIn = ps * 16 + nn * 8 + 2 * t;
                float e0 = ((mw0 >> sIn) & 1u)       ? 0.f : __expf(sacc[nn][0] * SCALE);
                float e1 = ((mw0 >> (sIn + 1)) & 1u) ? 0.f : __expf(sacc[nn][1] * SCALE);
                float e2 = ((mw1 >> sIn) & 1u)       ? 0.f : __expf(sacc[nn][2] * SCALE);
                float e3 = ((mw1 >> (sIn + 1)) & 1u) ? 0.f : __expf(sacc[nn][3] * SCALE);
                zl += e0 + e1;
                zh += e2 + e3;
                float* wr = outW + (mrow0 + pid * 16 + g) * (size_t)SK + st + sIn;
                *(float2*)wr = make_float2(e0, e1);
                *(float2*)(wr + 8 * SK) = make_float2(e2, e3);
                uint32_t h01, l01, h23, l23;
                split2(e0, e1, h01, l01);
                split2(e2, e3, h23, l23);
                int row = pid * 16 + g;
                *(uint32_t*)(sm + SPH + row * 80 + sIn * 2) = h01;
                *(uint32_t*)(sm + SPL + row * 80 + sIn * 2) = l01;
                *(uint32_t*)(sm + SPH + (row + 8) * 80 + sIn * 2) = h23;
                *(uint32_t*)(sm + SPL + (row + 8) * 80 + sIn * 2) = l23;
            }
        }
        asm volatile("bar.sync %0, 64;" :: "r"(pid + 1) : "memory");  // pair barrier

        // ---- PV: rows pid*16..+16 x d-half ps*64..+64, full s(32) ----
        #pragma unroll
        for (int kc = 0; kc < 2; kc++) {
            uint32_t pah[4], pal[4];
            ldm_x4(pah, pbase + kc * 32);
            ldm_x4(pal, pbase + kc * 32 + 5120);
            #pragma unroll
            for (int dpp = 0; dpp < 4; dpp++) {
                uint32_t vb = sb + SVH + (uint32_t)(ps * 64 + dpp * 16 + bRow) * 80
                            + bCol + kc * 32;
                uint32_t vh[4], vl[4];
                ldm_x4(vh, vb);
                ldm_x4(vl, vb + 10240);
                mma_bf16(X[2 * dpp],     pah, vh[0], vh[1]);
                mma_bf16(X[2 * dpp + 1], pah, vh[2], vh[3]);
                mma_bf16(X[2 * dpp],     pal, vh[0], vh[1]);
                mma_bf16(X[2 * dpp + 1], pal, vh[2], vh[3]);
                mma_bf16(X[2 * dpp],     pah, vl[0], vl[1]);
                mma_bf16(X[2 * dpp + 1], pah, vl[2], vl[3]);
            }
        }
        __syncthreads();   // all reads of K/VT/P done before next stage
    }

    // ---- Z: reduce over t lanes, then across the warp pair via smem ----
    zl += __shfl_xor_sync(0xffffffffu, zl, 1);
    zl += __shfl_xor_sync(0xffffffffu, zl, 2);
    zh += __shfl_xor_sync(0xffffffffu, zh, 1);
    zh += __shfl_xor_sync(0xffffffffu, zh, 2);
    float* Zs = (float*)(sm + SZ);
    if (t == 0) {
        Zs[ps * 64 + pid * 16 + g]     = zl;
        Zs[ps * 64 + pid * 16 + g + 8] = zh;
    }
    asm volatile("bar.sync %0, 64;" :: "r"(pid + 1) : "memory");
    float invl = 1.f / (Zs[pid * 16 + g]     + Zs[64 + pid * 16 + g]);
    float invh = 1.f / (Zs[pid * 16 + g + 8] + Zs[64 + pid * 16 + g + 8]);
    if (ps == 0 && t == 0) {
        g_invZ[mrow0 + pid * 16 + g]     = invl;
        g_invZ[mrow0 + pid * 16 + g + 8] = invh;
    }

    // ---- store X (normalized): d cols ps*64 + dpp*16 + j*8 + 2t ----
    #pragma unroll
    for (int nn = 0; nn < 8; nn++) {
        int dcol = ps * 64 + (nn >> 1) * 16 + (nn & 1) * 8 + 2 * t;
        float* xr = outX + (mrow0 + pid * 16 + g) * (size_t)DD + dcol;
        *(float2*)xr = make_float2(X[nn][0] * invl, X[nn][1] * invl);
        *(float2*)(xr + 8 * DD) = make_float2(X[nn][2] * invh, X[nn][3] * invh);
    }
}

// ---------------- kernel: W *= invZ[row] ----------------
__global__ __launch_bounds__(256)
void norm_w_kernel(float4* __restrict__ W)
{
    size_t i = (size_t)blockIdx.x * 256 + threadIdx.x;
    float inv = g_invZ[i >> 9];
    float4 v = W[i];
    v.x *= inv; v.y *= inv; v.z *= inv; v.w *= inv;
    W[i] = v;
}

extern "C" void kernel_launch(void* const* d_in, const int* in_sizes, int n_in,
                              void* d_out, int out_size)
{
    (void)in_sizes; (void)n_in; (void)out_size;
    const float* Q = (const float*)d_in[0];
    const float* K = (const float*)d_in[1];
    const float* V = (const float*)d_in[2];
    const void*  M = d_in[3];

    float* outX = (float*)d_out;                    // (N, L, D)
    float* outW = outX + (size_t)NB * LQ * DD;      // (N, L, S)

    cudaFuncSetAttribute(attn_mma2, cudaFuncAttributeMaxDynamicSharedMemorySize,
                         SMEM_TOTAL);

    detect_mask_kind<<<1, 256>>>((const unsigned char*)M);
    prep_splitqk<<<NB * LQ * DD / 4 / 256, 256>>>(Q, K);
    prep_vt<<<NB * DD * (SK / 8) / 256, 256>>>(V);
    prep_mask<<<NB * LQ / 8, 256>>>(M);

    dim3 grid(LQ / 64, NB);
    attn_mma2<<<grid, THREADS, SMEM_TOTAL>>>(outX, outW);

    size_t nw4 = (size_t)NB * LQ * SK / 4;
    norm_w_kernel<<<(unsigned)(nw4 / 256), 256>>>((float4*)outW);
}

// round 9
// speedup vs baseline: 5.0706x; 1.0767x over previous
#include <cuda_runtime.h>
#include <cuda_bf16.h>
#include <cstdint>

constexpr int NB = 16, LQ = 2048, SK = 2048, DD = 128;
constexpr int TS = 32, NT = SK / TS;      // 64 key tiles
constexpr int THREADS = 256;
constexpr float SCALE = 0.08838834764831845f;  // 1/sqrt(128)

// ---- smem layout (bytes) ----
constexpr int SQH = 0;         // Q hi: 64 rows x 272B
constexpr int SQL = 17408;     // Q lo
constexpr int SKH = 34816;     // K hi: 32 rows x 272B
constexpr int SKL = 43520;     // K lo
constexpr int SVH = 52224;     // VT hi: 128 rows x 80B
constexpr int SVL = 62464;     // VT lo
constexpr int SPH = 72704;     // P hi: 64 rows x 80B
constexpr int SPL = 77824;     // P lo
constexpr int SMB = 82944;     // mask bits: 64 words
constexpr int SZ  = 83200;     // Z: 2 x 64 floats
constexpr int SMEM_TOTAL = 83712;

// ---- pre-split operands in device globals ----
__device__ __align__(16) __nv_bfloat16 gQh[NB * LQ * DD], gQl[NB * LQ * DD];
__device__ __align__(16) __nv_bfloat16 gKh[NB * SK * DD], gKl[NB * SK * DD];
__device__ __align__(16) __nv_bfloat16 gVh[NB * DD * SK], gVl[NB * DD * SK]; // [n][d][s]
__device__ int   g_mask_kind;
__device__ float g_invZ[NB * LQ];

__device__ __forceinline__ bool mask_at(const void* M, int kind, size_t idx)
{
    if (kind == 1) return ((const int*)M)[idx] != 0;
    if (kind == 0) return ((const unsigned char*)M)[idx] != 0;
    return ((const float*)M)[idx] != 0.0f;
}

// ---------------- small helpers ----------------
__device__ __forceinline__ uint32_t smem_u32(const void* p) {
    uint32_t a;
    asm("{ .reg .u64 t; cvta.to.shared.u64 t, %1; cvt.u32.u64 %0, t; }" : "=r"(a) : "l"(p));
    return a;
}
__device__ __forceinline__ uint32_t pack_bf16(float a, float b) {
    __nv_bfloat16 ah = __float2bfloat16(a), bh = __float2bfloat16(b);
    return (uint32_t)*(uint16_t*)&ah | ((uint32_t)*(uint16_t*)&bh << 16);
}
__device__ __forceinline__ void split2(float a, float b, uint32_t& h, uint32_t& l) {
    __nv_bfloat16 ah = __float2bfloat16(a), bh = __float2bfloat16(b);
    float ahf = __bfloat162float(ah), bhf = __bfloat162float(bh);
    h = (uint32_t)*(uint16_t*)&ah | ((uint32_t)*(uint16_t*)&bh << 16);
    l = pack_bf16(a - ahf, b - bhf);
}
__device__ __forceinline__ void mma_bf16(float* c, const uint32_t* a, uint32_t b0, uint32_t b1) {
    asm volatile(
        "mma.sync.aligned.m16n8k16.row.col.f32.bf16.bf16.f32 "
        "{%0,%1,%2,%3}, {%4,%5,%6,%7}, {%8,%9}, {%0,%1,%2,%3};"
        : "+f"(c[0]), "+f"(c[1]), "+f"(c[2]), "+f"(c[3])
        : "r"(a[0]), "r"(a[1]), "r"(a[2]), "r"(a[3]), "r"(b0), "r"(b1));
}
__device__ __forceinline__ void ldm_x4(uint32_t* r, uint32_t addr) {
    asm volatile("ldmatrix.sync.aligned.m8n8.x4.shared.b16 {%0,%1,%2,%3}, [%4];"
                 : "=r"(r[0]), "=r"(r[1]), "=r"(r[2]), "=r"(r[3]) : "r"(addr));
}
__device__ __forceinline__ void cp16(uint32_t dst, const void* src) {
    asm volatile("cp.async.ca.shared.global [%0], [%1], 16;" :: "r"(dst), "l"(src) : "memory");
}
__device__ __forceinline__ void cp_commit_wait0() {
    asm volatile("cp.async.commit_group;" ::: "memory");
    asm volatile("cp.async.wait_group 0;" ::: "memory");
}

// ---------------- prep kernels ----------------
// A: split Q,K fp32 -> bf16 hi/lo (same layout); block 0 also detects mask dtype
__global__ __launch_bounds__(256)
void prep_splitqk(const float* __restrict__ Q, const float* __restrict__ K,
                  const unsigned char* __restrict__ M)
{
    size_t i = (size_t)blockIdx.x * 256 + threadIdx.x;   // float4 idx, NB*LQ*DD/4 total
    float4 q = ((const float4*)Q)[i];
    float4 k = ((const float4*)K)[i];
    uint2 H, L;
    split2(q.x, q.y, H.x, L.x); split2(q.z, q.w, H.y, L.y);
    ((uint2*)gQh)[i] = H; ((uint2*)gQl)[i] = L;
    split2(k.x, k.y, H.x, L.x); split2(k.z, k.w, H.y, L.y);
    ((uint2*)gKh)[i] = H; ((uint2*)gKl)[i] = L;

    // mask dtype detection (0=u8, 1=i32, 2=f32) by block 0
    if (blockIdx.x == 0) {
        __shared__ int off1, off23;
        if (threadIdx.x == 0) { off1 = 0; off23 = 0; }
        __syncthreads();
        int b1 = 0, b23 = 0;
        for (int j = threadIdx.x; j < 16384; j += 256) {
            unsigned char v = M[j];
            int off = j & 3;
            if (v) { if (off == 1) b1 = 1; if (off >= 2) b23 = 1; }
        }
        if (b1)  atomicOr(&off1, 1);
        if (b23) atomicOr(&off23, 1);
        __syncthreads();
        if (threadIdx.x == 0) g_mask_kind = off1 ? 0 : (off23 ? 2 : 1);
    }
}

// B: V fp32 [n][s][d] -> VT bf16 hi/lo [n][d][s]
__global__ __launch_bounds__(256)
void prep_vt(const float* __restrict__ V)
{
    size_t i = (size_t)blockIdx.x * 256 + threadIdx.x;   // (n,d,s8): NB*DD*(SK/8)
    int s8 = (int)(i & 255);
    int d  = (int)((i >> 8) & 127);
    int n  = (int)(i >> 15);
    const float* vp = V + ((size_t)n * SK + s8 * 8) * DD + d;
    float f[8];
    #pragma unroll
    for (int j = 0; j < 8; j++) f[j] = vp[(size_t)j * DD];
    uint4 H, L;
    split2(f[0], f[1], H.x, L.x); split2(f[2], f[3], H.y, L.y);
    split2(f[4], f[5], H.z, L.z); split2(f[6], f[7], H.w, L.w);
    ((uint4*)gVh)[i] = H; ((uint4*)gVl)[i] = L;
}

// ---------------- main attention kernel ----------------
__global__ __launch_bounds__(THREADS, 2)
void attn_mma2(const void* __restrict__ M,
               float* __restrict__ outX, float* __restrict__ outW)
{
    extern __shared__ char sm[];
    const int n = blockIdx.y, q0 = blockIdx.x * 64;
    const int tid = threadIdx.x, lane = tid & 31, w = tid >> 5;
    const int pid = w >> 1, ps = w & 1;       // pair id 0..3, side 0/1
    const int g = lane >> 2, t = lane & 3;
    const size_t mrow0 = (size_t)n * LQ + q0;
    const uint32_t sb = smem_u32(sm);
    const int mkind = g_mask_kind;

    // ldmatrix per-lane geometry (validated)
    const int mat = lane >> 3, mr = lane & 7;
    const int bRow = ((mat >> 1) << 3) + mr;
    const int bCol = (mat & 1) << 4;
    const int aRow = ((mat & 1) << 3) + mr;
    const int aCol = (mat >> 1) << 4;

    // ---- stage Q (persistent) ----
    {
        const char* qh = (const char*)gQh + mrow0 * DD * 2;
        const char* ql = (const char*)gQl + mrow0 * DD * 2;
        for (int c = tid; c < 1024; c += THREADS) {   // 64 rows x 16 chunks
            int r = c >> 4, cx = (c & 15) * 16;
            cp16(sb + SQH + r * 272 + cx, qh + r * 256 + cx);
            cp16(sb + SQL + r * 272 + cx, ql + r * 256 + cx);
        }
        cp_commit_wait0();
        __syncthreads();
    }

    float X[8][4];
    #pragma unroll
    for (int i = 0; i < 8; i++)
        #pragma unroll
        for (int j = 0; j < 4; j++) X[i][j] = 0.f;
    float zl = 0.f, zh = 0.f;

    const uint32_t qbase = sb + SQH + (uint32_t)(pid * 16 + aRow) * 272 + aCol;
    const uint32_t kbase = sb + SKH + (uint32_t)(ps * 16 + bRow) * 272 + bCol;
    const uint32_t pbase = sb + SPH + (uint32_t)(pid * 16 + aRow) * 80 + aCol;

    for (int tt = 0; tt < NT; tt++) {
        const int st = tt * TS;

        // ---- cp.async stage K, VT; mask bits via LDG+ballot (overlaps) ----
        {
            const char* kh = (const char*)gKh + ((size_t)n * SK + st) * DD * 2;
            const char* kl = (const char*)gKl + ((size_t)n * SK + st) * DD * 2;
            const char* vh = (const char*)gVh + ((size_t)n * DD * SK + st) * 2;
            const char* vl = (const char*)gVl + ((size_t)n * DD * SK + st) * 2;
            for (int c = tid; c < 512; c += THREADS) {
                int r = c >> 4, cx = (c & 15) * 16;        // K: 32 rows x 16
                cp16(sb + SKH + r * 272 + cx, kh + r * 256 + cx);
                cp16(sb + SKL + r * 272 + cx, kl + r * 256 + cx);
                int vr = c >> 2, vx = (c & 3) * 16;        // VT: 128 rows x 4
                cp16(sb + SVH + vr * 80 + vx, vh + (size_t)vr * 4096 + vx);
                cp16(sb + SVL + vr * 80 + vx, vl + (size_t)vr * 4096 + vx);
            }
            // mask bits: each warp packs 8 rows (coalesced 128B reads, read once grid-wide)
            #pragma unroll
            for (int rr = 0; rr < 8; rr++) {
                int r = w + rr * 8;
                bool mk = mask_at(M, mkind, (mrow0 + r) * SK + st + lane);
                uint32_t bits = __ballot_sync(0xffffffffu, mk);
                if (lane == 0) *(uint32_t*)(sm + SMB + r * 4) = bits;
            }
            cp_commit_wait0();
        }
        __syncthreads();

        // ---- QK: rows pid*16..+16 x s-sub ps*16..+16, 3-pass hi/lo ----
        float sacc[2][4] = {{0.f,0.f,0.f,0.f},{0.f,0.f,0.f,0.f}};
        #pragma unroll
        for (int kc = 0; kc < 8; kc++) {
            uint32_t qh[4], ql[4], bh[4], bl[4];
            ldm_x4(qh, qbase + kc * 32);
            ldm_x4(ql, qbase + kc * 32 + 17408);
            ldm_x4(bh, kbase + kc * 32);
            ldm_x4(bl, kbase + kc * 32 + 8704);
            mma_bf16(sacc[0], qh, bh[0], bh[1]);
            mma_bf16(sacc[1], qh, bh[2], bh[3]);
            mma_bf16(sacc[0], ql, bh[0], bh[1]);
            mma_bf16(sacc[1], ql, bh[2], bh[3]);
            mma_bf16(sacc[0], qh, bl[0], bl[1]);
            mma_bf16(sacc[1], qh, bl[2], bl[3]);
        }

        // ---- epilogue: mask, exp, Z, W write, P -> smem ----
        {
            const uint32_t* MB = (const uint32_t*)(sm + SMB);
            uint32_t mw0 = MB[pid * 16 + g];
            uint32_t mw1 = MB[pid * 16 + g + 8];
            #pragma unroll
            for (int nn = 0; nn < 2; nn++) {
                int sIn = ps * 16 + nn * 8 + 2 * t;
                float e0 = ((mw0 >> sIn) & 1u)       ? 0.f : __expf(sacc[nn][0] * SCALE);
                float e1 = ((mw0 >> (sIn + 1)) & 1u) ? 0.f : __expf(sacc[nn][1] * SCALE);
                float e2 = ((mw1 >> sIn) & 1u)       ? 0.f : __expf(sacc[nn][2] * SCALE);
                float e3 = ((mw1 >> (sIn + 1)) & 1u) ? 0.f : __expf(sacc[nn][3] * SCALE);
                zl += e0 + e1;
                zh += e2 + e3;
                float* wr = outW + (mrow0 + pid * 16 + g) * (size_t)SK + st + sIn;
                *(float2*)wr = make_float2(e0, e1);
                *(float2*)(wr + 8 * SK) = make_float2(e2, e3);
                uint32_t h01, l01, h23, l23;
                split2(e0, e1, h01, l01);
                split2(e2, e3, h23, l23);
                int row = pid * 16 + g;
                *(uint32_t*)(sm + SPH + row * 80 + sIn * 2) = h01;
                *(uint32_t*)(sm + SPL + row * 80 + sIn * 2) = l01;
                *(uint32_t*)(sm + SPH + (row + 8) * 80 + sIn * 2) = h23;
                *(uint32_t*)(sm + SPL + (row + 8) * 80 + sIn * 2) = l23;
            }
        }
        asm volatile("bar.sync %0, 64;" :: "r"(pid + 1) : "memory");  // pair barrier

        // ---- PV: rows pid*16..+16 x d-half ps*64..+64, full s(32) ----
        #pragma unroll
        for (int kc = 0; kc < 2; kc++) {
            uint32_t pah[4], pal[4];
            ldm_x4(pah, pbase + kc * 32);
            ldm_x4(pal, pbase + kc * 32 + 5120);
            #pragma unroll
            for (int dpp = 0; dpp < 4; dpp++) {
                uint32_t vb = sb + SVH + (uint32_t)(ps * 64 + dpp * 16 + bRow) * 80
                            + bCol + kc * 32;
                uint32_t vh[4], vl[4];
                ldm_x4(vh, vb);
                ldm_x4(vl, vb + 10240);
                mma_bf16(X[2 * dpp],     pah, vh[0], vh[1]);
                mma_bf16(X[2 * dpp + 1], pah, vh[2], vh[3]);
                mma_bf16(X[2 * dpp],     pal, vh[0], vh[1]);
                mma_bf16(X[2 * dpp + 1], pal, vh[2], vh[3]);
                mma_bf16(X[2 * dpp],     pah, vl[0], vl[1]);
                mma_bf16(X[2 * dpp + 1], pah, vl[2], vl[3]);
            }
        }
        __syncthreads();   // all reads of K/VT/P done before next stage
    }

    // ---- Z: reduce over t lanes, then across the warp pair via smem ----
    zl += __shfl_xor_sync(0xffffffffu, zl, 1);
    zl += __shfl_xor_sync(0xffffffffu, zl, 2);
    zh += __shfl_xor_sync(0xffffffffu, zh, 1);
    zh += __shfl_xor_sync(0xffffffffu, zh, 2);
    float* Zs = (float*)(sm + SZ);
    if (t == 0) {
        Zs[ps * 64 + pid * 16 + g]     = zl;
        Zs[ps * 64 + pid * 16 + g + 8] = zh;
    }
    asm volatile("bar.sync %0, 64;" :: "r"(pid + 1) : "memory");
    float invl = 1.f / (Zs[pid * 16 + g]     + Zs[64 + pid * 16 + g]);
    float invh = 1.f / (Zs[pid * 16 + g + 8] + Zs[64 + pid * 16 + g + 8]);
    if (ps == 0 && t == 0) {
        g_invZ[mrow0 + pid * 16 + g]     = invl;
        g_invZ[mrow0 + pid * 16 + g + 8] = invh;
    }

    // ---- store X (normalized) ----
    #pragma unroll
    for (int nn = 0; nn < 8; nn++) {
        int dcol = ps * 64 + (nn >> 1) * 16 + (nn & 1) * 8 + 2 * t;
        float* xr = outX + (mrow0 + pid * 16 + g) * (size_t)DD + dcol;
        *(float2*)xr = make_float2(X[nn][0] * invl, X[nn][1] * invl);
        *(float2*)(xr + 8 * DD) = make_float2(X[nn][2] * invh, X[nn][3] * invh);
    }
}

// ---------------- kernel: W *= invZ[row] ----------------
__global__ __launch_bounds__(256)
void norm_w_kernel(float4* __restrict__ W)
{
    size_t i = (size_t)blockIdx.x * 256 + threadIdx.x;
    float inv = g_invZ[i >> 9];
    float4 v = W[i];
    v.x *= inv; v.y *= inv; v.z *= inv; v.w *= inv;
    W[i] = v;
}

extern "C" void kernel_launch(void* const* d_in, const int* in_sizes, int n_in,
                              void* d_out, int out_size)
{
    (void)in_sizes; (void)n_in; (void)out_size;
    const float* Q = (const float*)d_in[0];
    const float* K = (const float*)d_in[1];
    const float* V = (const float*)d_in[2];
    const void*  M = d_in[3];

    float* outX = (float*)d_out;                    // (N, L, D)
    float* outW = outX + (size_t)NB * LQ * DD;      // (N, L, S)

    cudaFuncSetAttribute(attn_mma2, cudaFuncAttributeMaxDynamicSharedMemorySize,
                         SMEM_TOTAL);

    prep_splitqk<<<NB * LQ * DD / 4 / 256, 256>>>(Q, K, (const unsigned char*)M);
    prep_vt<<<NB * DD * (SK / 8) / 256, 256>>>(V);

    dim3 grid(LQ / 64, NB);
    attn_mma2<<<grid, THREADS, SMEM_TOTAL>>>(M, outX, outW);

    size_t nw4 = (size_t)NB * LQ * SK / 4;
    norm_w_kernel<<<(unsigned)(nw4 / 256), 256>>>((float4*)outW);
}